// round 4
// baseline (speedup 1.0000x reference)
#include <cuda_runtime.h>
#include <stdint.h>

#define BB 4
#define NN 2000
#define CC 80
#define NCLS 81
#define KPRE 2000
#define MAXOUT 100
#define CAP 8192
#define SCAP 4096
#define NHIST 5120
#define HBASE 0x1EA66
#define SCORE_THR 0.05f
#define IOU_THR 0.5f
#define MAX_RATIO 4.135166556742356f

// ------------------- scratch (device globals; self-cleaning, no allocation) ----
__device__ int                g_cnt[BB];          // zeroed by k_mid after read
__device__ int                g_hist[BB][NHIST];  // zeroed by k_mid after read
__device__ unsigned long long g_keys[BB][CAP];    // only [0,cnt) ever read
__device__ unsigned long long g_skeys[BB][SCAP];  // zeroed by k_nms_out after read
__device__ float4             g_box[BB][KPRE];    // fully overwritten each run
__device__ float4             g_obox[BB][KPRE];
__device__ float              g_oarea[BB][KPRE];
__device__ int                g_label[BB][KPRE];
__device__ unsigned int       g_mask[BB][KPRE][64];
__device__ int                g_outidx[BB][MAXOUT];

__device__ __forceinline__ int bucket_of(unsigned bits) {
    int b = (int)(bits >> 13) - HBASE;
    return min(NHIST - 1, max(0, b));
}

// ------------------- softmax + threshold + warp-aggregated compact + histogram --
__global__ void k_softmax(const float* __restrict__ cls) {
    int warp = (blockIdx.x * blockDim.x + threadIdx.x) >> 5;
    int lane = threadIdx.x & 31;
    if (warp >= BB * NN) return;
    int img = warp / NN, p = warp % NN;
    const float* row = cls + ((size_t)img * NN + p) * NCLS;

    float x0 = row[lane];
    float x1 = row[lane + 32];
    float x2 = (lane < NCLS - 64) ? row[lane + 64] : -1e30f;
    float m = fmaxf(fmaxf(x0, x1), x2);
    #pragma unroll
    for (int o = 16; o; o >>= 1) m = fmaxf(m, __shfl_xor_sync(0xffffffffu, m, o));

    float e0 = expf(x0 - m);
    float e1 = expf(x1 - m);
    float e2 = (lane < NCLS - 64) ? expf(x2 - m) : 0.0f;
    float s = e0 + e1 + e2;
    #pragma unroll
    for (int o = 16; o; o >>= 1) s += __shfl_xor_sync(0xffffffffu, s, o);

    float sc0 = __fdiv_rn(e0, s);
    float sc1 = __fdiv_rn(e1, s);
    float sc2 = __fdiv_rn(e2, s);
    bool p0 = sc0 > SCORE_THR;                       // classes 0..31
    bool p1 = sc1 > SCORE_THR;                       // classes 32..63
    bool p2 = (lane < CC - 64) && (sc2 > SCORE_THR); // classes 64..79
    unsigned b0 = __ballot_sync(0xffffffffu, p0);
    unsigned b1 = __ballot_sync(0xffffffffu, p1);
    unsigned b2 = __ballot_sync(0xffffffffu, p2);
    int tot = __popc(b0) + __popc(b1) + __popc(b2);
    int base = 0;
    if (lane == 0 && tot) base = atomicAdd(&g_cnt[img], tot);
    base = __shfl_sync(0xffffffffu, base, 0);
    unsigned lm = (1u << lane) - 1u;

    #pragma unroll
    for (int grp = 0; grp < 3; grp++) {
        bool pr = (grp == 0) ? p0 : (grp == 1) ? p1 : p2;
        if (pr) {
            float sc = (grp == 0) ? sc0 : (grp == 1) ? sc1 : sc2;
            int c = lane + grp * 32;
            int rank = ((grp > 0) ? __popc(b0) : 0) + ((grp > 1) ? __popc(b1) : 0) +
                       __popc(((grp == 0) ? b0 : (grp == 1) ? b1 : b2) & lm);
            int pos = base + rank;
            if (pos < CAP) {
                unsigned flat = (unsigned)(p * CC + c);
                unsigned sb = __float_as_uint(sc);
                g_keys[img][pos] =
                    ((unsigned long long)sb << 32) | (unsigned long long)(~flat);
                atomicAdd(&g_hist[img][bucket_of(sb)], 1);
            }
        }
    }
}

// ------------------- fused: suffix-scan + scatter + segsort + decode (1 blk/img) -
#define SCAN_U (NHIST / 1024)   /* 5 */
__global__ void k_mid(const float* __restrict__ reg,
                      const float* __restrict__ props,
                      const int* __restrict__ hw) {
    __shared__ int s_off[NHIST];
    __shared__ int s_bc[NHIST];
    __shared__ int s_wtot[32];
    int img = blockIdx.x, t = threadIdx.x;  // 1024
    int lane = t & 31, wid = t >> 5;

    // ---- phase 1: read histogram (descending buckets), zero it, suffix scan ----
    int cnt[SCAN_U];
    int tsum = 0;
    #pragma unroll
    for (int u = 0; u < SCAN_U; u++) {
        int b = NHIST - 1 - (t * SCAN_U + u);
        cnt[u] = g_hist[img][b];
        g_hist[img][b] = 0;
        s_bc[b] = 0;
        tsum += cnt[u];
    }
    int ws = tsum;
    #pragma unroll
    for (int o = 1; o < 32; o <<= 1) {
        int v = __shfl_up_sync(0xffffffffu, ws, o);
        if (lane >= o) ws += v;
    }
    if (lane == 31) s_wtot[wid] = ws;
    __syncthreads();
    if (wid == 0) {
        int v = s_wtot[lane];
        int sv = v;
        #pragma unroll
        for (int o = 1; o < 32; o <<= 1) {
            int x = __shfl_up_sync(0xffffffffu, sv, o);
            if (lane >= o) sv += x;
        }
        s_wtot[lane] = sv - v;
    }
    __syncthreads();
    int base = s_wtot[wid] + (ws - tsum);
    #pragma unroll
    for (int u = 0; u < SCAN_U; u++) {
        int b = NHIST - 1 - (t * SCAN_U + u);
        s_off[b] = base;
        base += cnt[u];
    }
    int total = min(g_cnt[img], CAP);
    __syncthreads();

    // ---- phase 2: scatter keys to final bucket-ordered slots (smem counters) ---
    for (int e = t; e < total; e += 1024) {
        unsigned long long key = g_keys[img][e];
        int b = bucket_of((unsigned)(key >> 32));
        int o = s_off[b];
        if (o < 2048) {
            int pos = o + atomicAdd(&s_bc[b], 1);
            if (pos < SCAP) g_skeys[img][pos] = key;
        }
    }
    if (t == 0) g_cnt[img] = 0;
    __syncthreads();

    // ---- phase 3: per-bucket insertion sort (descending by full key) -----------
    #pragma unroll
    for (int u = 0; u < SCAN_U; u++) {
        int b = NHIST - 1 - (t * SCAN_U + u);
        int o = s_off[b];
        if (o < 2048) {
            int end = min(o + s_bc[b], SCAP);
            unsigned long long* a = &g_skeys[img][0];
            for (int i = o + 1; i < end; i++) {
                unsigned long long v = a[i];
                int j = i - 1;
                while (j >= o && a[j] < v) { a[j + 1] = a[j]; j--; }
                a[j + 1] = v;
            }
        }
    }
    __syncthreads();

    // ---- phase 4: decode top-2000 (no FMA contraction; matches reference fp) ---
    for (int r = t; r < KPRE; r += 1024) {
        unsigned long long key = g_skeys[img][r];
        float sc = __uint_as_float((unsigned)(key >> 32));
        if (sc > SCORE_THR) {
            int flat = (int)(~(unsigned)key);
            int p = flat / CC, c = flat % CC;
            const float* pb = props + ((size_t)img * NN + p) * 4;
            const float* dd = reg + (((size_t)img * NN + p) * CC + c) * 4;
            float h = (float)hw[img * 2 + 0];
            float w = (float)hw[img * 2 + 1];

            float dx = __fmul_rn(dd[0], 0.1f);
            float dy = __fmul_rn(dd[1], 0.1f);
            float dw = fminf(fmaxf(__fmul_rn(dd[2], 0.2f), -MAX_RATIO), MAX_RATIO);
            float dh = fminf(fmaxf(__fmul_rn(dd[3], 0.2f), -MAX_RATIO), MAX_RATIO);

            float px = __fmul_rn(__fadd_rn(pb[0], pb[2]), 0.5f);
            float py = __fmul_rn(__fadd_rn(pb[1], pb[3]), 0.5f);
            float pw = __fsub_rn(pb[2], pb[0]);
            float ph = __fsub_rn(pb[3], pb[1]);

            float gx = __fadd_rn(px, __fmul_rn(pw, dx));
            float gy = __fadd_rn(py, __fmul_rn(ph, dy));
            float gw = __fmul_rn(pw, expf(dw));
            float gh = __fmul_rn(ph, expf(dh));
            float hx = __fmul_rn(gw, 0.5f);
            float hy = __fmul_rn(gh, 0.5f);

            float x1 = fminf(fmaxf(__fsub_rn(gx, hx), 0.0f), w);
            float y1 = fminf(fmaxf(__fsub_rn(gy, hy), 0.0f), h);
            float x2 = fminf(fmaxf(__fadd_rn(gx, hx), 0.0f), w);
            float y2 = fminf(fmaxf(__fadd_rn(gy, hy), 0.0f), h);

            g_box[img][r] = make_float4(x1, y1, x2, y2);
            float off = __fmul_rn((float)c, __fadd_rn(fmaxf(h, w), 1.0f));
            float4 ob = make_float4(__fadd_rn(x1, off), __fadd_rn(y1, off),
                                    __fadd_rn(x2, off), __fadd_rn(y2, off));
            g_obox[img][r] = ob;
            g_oarea[img][r] = __fmul_rn(__fsub_rn(ob.z, ob.x), __fsub_rn(ob.w, ob.y));
            g_label[img][r] = c;
        } else {
            g_box[img][r] = make_float4(0, 0, 0, 0);
            g_obox[img][r] = make_float4(0, 0, 0, 0);
            g_oarea[img][r] = 0.0f;
            g_label[img][r] = -1;
        }
    }
}

// ------------------- suppression mask matrix (upper triangle only) -------------
#define ROWS_PB 32
__global__ void k_mask() {
    __shared__ float4 sb[KPRE];
    __shared__ float sa[KPRE];
    int img = blockIdx.y;
    int tid = threadIdx.x;  // 256
    for (int e = tid; e < KPRE; e += 256) {
        sb[e] = g_obox[img][e];
        sa[e] = g_oarea[img][e];
    }
    __syncthreads();
    int warp = tid >> 5, lane = tid & 31;
    #pragma unroll
    for (int rr = 0; rr < 4; rr++) {
        int i = blockIdx.x * ROWS_PB + warp * 4 + rr;
        if (i >= KPRE) continue;
        float4 bi = sb[i];
        float ai = sa[i];
        int w0 = i >> 5;
        for (int z = lane; z < w0; z += 32) g_mask[img][i][z] = 0u;
        for (int ch = w0; ch < 64; ch++) {
            int j = ch * 32 + lane;
            bool pred = false;
            if (j < KPRE && j > i) {
                float4 bj = sb[j];
                float ltx = fmaxf(bi.x, bj.x), lty = fmaxf(bi.y, bj.y);
                float rbx = fminf(bi.z, bj.z), rby = fminf(bi.w, bj.w);
                float wx = fmaxf(__fsub_rn(rbx, ltx), 0.0f);
                float wy = fmaxf(__fsub_rn(rby, lty), 0.0f);
                float inter = __fmul_rn(wx, wy);
                float denom = __fadd_rn(__fsub_rn(__fadd_rn(ai, sa[j]), inter), 1e-6f);
                pred = __fdiv_rn(inter, denom) > IOU_THR;
            }
            unsigned m = __ballot_sync(0xffffffffu, pred);
            if (lane == 0) g_mask[img][i][ch] = m;
        }
    }
}

// ------------------- greedy NMS (16-row blocks, double-buffered) + emit --------
#define NBS (KPRE / 16)   /* 125 */
__global__ void k_nms_out(float* __restrict__ out) {
    int img = blockIdx.x;
    int lane = threadIdx.x;  // 32

    const unsigned long long* keys = g_skeys[img];
    unsigned r0 = 0, r1 = 0;  // bit set = suppressed
    #pragma unroll 4
    for (int b = 0; b < 32; b++) {
        int i0 = lane * 32 + b;
        float s0 = __uint_as_float((unsigned)(keys[i0] >> 32));
        if (!(s0 > SCORE_THR)) r0 |= (1u << b);
        int i1 = (lane + 32) * 32 + b;
        float s1 = (i1 < KPRE) ? __uint_as_float((unsigned)(keys[i1] >> 32)) : 0.0f;
        if (!(s1 > SCORE_THR)) r1 |= (1u << b);
    }

    const unsigned* mb = &g_mask[img][0][0];
    unsigned a0[16], a1[16], n0[16], n1[16];
    unsigned diag, ndiag;
    #pragma unroll
    for (int t = 0; t < 16; t++) {
        a0[t] = mb[t * 64 + lane];
        a1[t] = mb[t * 64 + lane + 32];
    }
    diag = (lane < 16) ? mb[lane * 64 + 0] : 0u;

    int outcnt = 0;
    for (int b = 0; b < NBS && outcnt < MAXOUT; b++) {
        int base = b * 16;
        int nbase = base + 16;
        if (b + 1 < NBS) {
            #pragma unroll
            for (int t = 0; t < 16; t++) {
                int row = nbase + t;
                n0[t] = mb[row * 64 + lane];
                n1[t] = mb[row * 64 + lane + 32];
            }
            ndiag = (lane < 16) ? mb[(nbase + lane) * 64 + (nbase >> 5)] : 0u;
        } else { ndiag = 0u; }

        int w = base >> 5, sh = base & 31;
        unsigned curw = (w < 32) ? __shfl_sync(0xffffffffu, r0, w)
                                 : __shfl_sync(0xffffffffu, r1, w - 32);
        unsigned rem = (~curw >> sh) & 0xFFFFu;
        unsigned kept = 0;
        while (rem) {
            int t = __ffs(rem) - 1;
            kept |= (1u << t);
            unsigned dg = __shfl_sync(0xffffffffu, diag, t);
            rem &= ~(((dg >> sh) & 0xFFFFu) | (1u << t));
        }
        #pragma unroll
        for (int t = 0; t < 16; t++)
            if ((kept >> t) & 1u) { r0 |= a0[t]; r1 |= a1[t]; }

        unsigned km = kept;
        while (km && outcnt < MAXOUT) {
            int t = __ffs(km) - 1; km &= km - 1;
            if (lane == 0) g_outidx[img][outcnt] = base + t;
            outcnt++;
        }
        #pragma unroll
        for (int t = 0; t < 16; t++) { a0[t] = n0[t]; a1[t] = n1[t]; }
        diag = ndiag;
    }
    if (lane == 0)
        for (int k = outcnt; k < MAXOUT; k++) g_outidx[img][k] = -1;
    __syncwarp();

    // emit: boxes[B,100,4] | scores[B,100] | labels[B,100]
    for (int k = lane; k < MAXOUT; k += 32) {
        int idx = g_outidx[img][k];
        float4 bx = make_float4(0, 0, 0, 0);
        float sc = 0.0f, lb = -1.0f;
        if (idx >= 0) {
            bx = g_box[img][idx];
            sc = __uint_as_float((unsigned)(keys[idx] >> 32));
            lb = (float)g_label[img][idx];
        }
        float* bo = out + (size_t)(img * MAXOUT + k) * 4;
        bo[0] = bx.x; bo[1] = bx.y; bo[2] = bx.z; bo[3] = bx.w;
        out[BB * MAXOUT * 4 + img * MAXOUT + k] = sc;
        out[BB * MAXOUT * 5 + img * MAXOUT + k] = lb;
    }
    __syncwarp();
    // self-clean skeys for the next run
    for (int i = lane; i < SCAP; i += 32) g_skeys[img][i] = 0ULL;
}

// ------------------- launch (4 kernels) ----------------------------------------
extern "C" void kernel_launch(void* const* d_in, const int* in_sizes, int n_in,
                              void* d_out, int out_size) {
    const float* cls = (const float*)d_in[0];
    const float* reg = (const float*)d_in[1];
    const float* props = (const float*)d_in[2];
    const int* hw = (const int*)d_in[3];
    float* out = (float*)d_out;

    k_softmax<<<(BB * NN * 32 + 255) / 256, 256>>>(cls);
    k_mid<<<BB, 1024>>>(reg, props, hw);
    dim3 mg((KPRE + ROWS_PB - 1) / ROWS_PB, BB);
    k_mask<<<mg, 256>>>();
    k_nms_out<<<BB, 32>>>(out);
}